// round 16
// baseline (speedup 1.0000x reference)
#include <cuda_runtime.h>
#include <cuda_bf16.h>
#include <cstdint>

#define NB 16
typedef unsigned long long u64;

#if defined(__CUDA_ARCH_FEAT_SM103_ALL) || defined(__CUDA_ARCH_FEAT_SM100_ALL) || \
    (defined(__CUDA_ARCH_SPECIFIC__) && (__CUDA_ARCH_SPECIFIC__ >= 1000))
#define HAS_TC 1
#else
#define HAS_TC 0
#endif

// ---------------------------------------------------------------------------
// PTX helpers
// ---------------------------------------------------------------------------
__device__ __forceinline__ uint32_t smem_u32(const void* p) {
    uint32_t a;
    asm("{ .reg .u64 t; cvta.to.shared.u64 t, %1; cvt.u32.u64 %0, t; }" : "=r"(a) : "l"(p));
    return a;
}
__device__ __forceinline__ float ex2f(float x) {
    float r; asm("ex2.approx.f32 %0, %1;" : "=f"(r) : "f"(x)); return r;
}
__device__ __forceinline__ float rcpf(float x) {
    float r; asm("rcp.approx.f32 %0, %1;" : "=f"(r) : "f"(x)); return r;
}
__device__ __forceinline__ uint32_t prmt_hi(uint32_t a, uint32_t b) {
    uint32_t r; asm("prmt.b32 %0, %1, %2, 0x7632;" : "=r"(r) : "r"(a), "r"(b)); return r;
}
__device__ __forceinline__ uint32_t cvt_bf16x2(float hi, float lo) {
    uint32_t r; asm("cvt.rn.bf16x2.f32 %0, %1, %2;" : "=r"(r) : "f"(hi), "f"(lo)); return r;
}
__device__ __forceinline__ float gatef(float a, float g) {
    float e1 = ex2f(fminf(a * -2.885390082f, 80.f));
    float e2 = ex2f(fminf(g * -1.442695041f, 80.f));
    float r  = rcpf((1.f + e1) * (1.f + e2));
    return (1.f - e1) * r;
}

#if HAS_TC
__device__ __forceinline__ uint32_t elect_one() {
    uint32_t p;
    asm volatile("{\n\t.reg .pred p;\n\telect.sync _|p, 0xFFFFFFFF;\n\tselp.b32 %0, 1, 0, p;\n\t}" : "=r"(p));
    return p;
}

#define TCGEN05_ALLOC(sm, n) \
    asm volatile("tcgen05.alloc.cta_group::1.sync.aligned.shared::cta.b32 [%0], %1;" \
                 :: "r"((uint32_t)(sm)), "r"((uint32_t)(n)) : "memory")
#define TCGEN05_RELINQ() \
    asm volatile("tcgen05.relinquish_alloc_permit.cta_group::1.sync.aligned;")
#define TCGEN05_DEALLOC(t, n) \
    asm volatile("tcgen05.dealloc.cta_group::1.sync.aligned.b32 %0, %1;" :: "r"(t), "r"((uint32_t)(n)))
#define TCGEN05_COMMIT(mb) \
    asm volatile("tcgen05.commit.cta_group::1.mbarrier::arrive::one.shared::cluster.b64 [%0];" \
                 :: "r"((uint32_t)(mb)) : "memory")
#define TCGEN05_FENCE_AFTER()  asm volatile("tcgen05.fence::after_thread_sync;" ::: "memory")
#define TCGEN05_FENCE_BEFORE() asm volatile("tcgen05.fence::before_thread_sync;" ::: "memory")
#define TCGEN05_WAIT_LD()      asm volatile("tcgen05.wait::ld.sync.aligned;" ::: "memory")
#define FENCE_ASYNC_SHARED()   asm volatile("fence.proxy.async.shared::cta;" ::: "memory")
#define MBARRIER_INIT(mb, c) \
    asm volatile("mbarrier.init.shared.b64 [%0], %1;" :: "r"((uint32_t)(mb)), "r"((uint32_t)(c)) : "memory")

#define MBAR_WAIT(mb, ph) do {                                                  \
    uint32_t _m = (uint32_t)(mb), _p = (uint32_t)(ph), _d;                      \
    asm volatile("{\n\t.reg .pred p;\n\t"                                       \
        "mbarrier.try_wait.parity.acquire.cta.shared::cta.b64 p, [%1], %2;\n\t" \
        "selp.b32 %0, 1, 0, p;\n\t}" : "=r"(_d) : "r"(_m), "r"(_p) : "memory"); \
    if (!_d) {                                                                  \
        asm volatile("{\n\t.reg .pred P1;\n\t"                                  \
            "WL_%=:\n\t"                                                        \
            "mbarrier.try_wait.parity.acquire.cta.shared::cta.b64 P1, [%0], %1, 0x989680;\n\t" \
            "@P1 bra.uni WD_%=;\n\t"                                            \
            "bra.uni WL_%=;\n\t"                                                \
            "WD_%=:\n\t}" :: "r"(_m), "r"(_p) : "memory");                      \
    }                                                                           \
} while (0)

#define LDTM_X32(r, a) \
    asm volatile("tcgen05.ld.sync.aligned.32x32b.x32.b32 " \
        "{%0,%1,%2,%3,%4,%5,%6,%7,%8,%9,%10,%11,%12,%13,%14,%15," \
        "%16,%17,%18,%19,%20,%21,%22,%23,%24,%25,%26,%27,%28,%29,%30,%31}, [%32];" \
        : "=r"((r)[0]),"=r"((r)[1]),"=r"((r)[2]),"=r"((r)[3]),"=r"((r)[4]),"=r"((r)[5]),"=r"((r)[6]),"=r"((r)[7]), \
          "=r"((r)[8]),"=r"((r)[9]),"=r"((r)[10]),"=r"((r)[11]),"=r"((r)[12]),"=r"((r)[13]),"=r"((r)[14]),"=r"((r)[15]), \
          "=r"((r)[16]),"=r"((r)[17]),"=r"((r)[18]),"=r"((r)[19]),"=r"((r)[20]),"=r"((r)[21]),"=r"((r)[22]),"=r"((r)[23]), \
          "=r"((r)[24]),"=r"((r)[25]),"=r"((r)[26]),"=r"((r)[27]),"=r"((r)[28]),"=r"((r)[29]),"=r"((r)[30]),"=r"((r)[31]) \
        : "r"(a))

#define LDTM_X16(r, a) \
    asm volatile("tcgen05.ld.sync.aligned.32x32b.x16.b32 " \
        "{%0,%1,%2,%3,%4,%5,%6,%7,%8,%9,%10,%11,%12,%13,%14,%15}, [%16];" \
        : "=r"((r)[0]),"=r"((r)[1]),"=r"((r)[2]),"=r"((r)[3]),"=r"((r)[4]),"=r"((r)[5]),"=r"((r)[6]),"=r"((r)[7]), \
          "=r"((r)[8]),"=r"((r)[9]),"=r"((r)[10]),"=r"((r)[11]),"=r"((r)[12]),"=r"((r)[13]),"=r"((r)[14]),"=r"((r)[15]) \
        : "r"(a))

__device__ __forceinline__ void mma_f16_ss(uint32_t d, u64 ad, u64 bd, uint32_t idesc, uint32_t en) {
    asm volatile("{\n\t.reg .pred p;\n\tsetp.ne.u32 p, %5, 0;\n\t"
        "tcgen05.mma.cta_group::1.kind::f16 [%0], %1, %2, %3, {%4,%4,%4,%4}, p;\n\t}"
        :: "r"(d), "l"(ad), "l"(bd), "r"(idesc), "r"(0u), "r"(en) : "memory");
}

static __device__ __forceinline__ u64 make_desc(uint32_t addr) {
    return (u64(2) << 61) | (u64(1) << 46) | (u64(64) << 32) | (u64(1) << 16)
         | ((u64)(addr >> 4) & 0x3FFF);
}

#define IDESC_W ((1u<<4) | (1u<<7) | (1u<<10) | (10u<<17) | (8u<<24))
#define IDESC_V ((1u<<4) | (1u<<7) | (1u<<10) | (8u<<17)  | (8u<<24))
#endif // HAS_TC

// ---------------------------------------------------------------------------
// Device scratch
// ---------------------------------------------------------------------------
__device__ __align__(16) __nv_bfloat16 g_wbh[4 * 160 * 320];
__device__ __align__(16) __nv_bfloat16 g_wbl[4 * 160 * 320];
__device__ __align__(16) char g_w1s [4][2][20480];
__device__ __align__(16) char g_wf0s[2][20480];
__device__ __align__(16) char g_wf1s[2][20480];
__device__ __align__(16) char g_embs[2][8][16384];
__device__ __align__(16) float g_w1t [4 * 80 * 80];
__device__ __align__(16) float g_wf0t[80 * 80];
__device__ __align__(16) float g_wf1t[80 * 80];
__device__ __align__(16) float g_e2  [512];
__device__ __align__(16) float g_bufA [16 * 80 * 4096];
__device__ __align__(16) float g_bufB [16 * 80 * 2048];
__device__ __align__(16) float g_bufAq[16 * 80 * 1024];
__device__ __align__(16) float g_bufBq[16 * 80 * 512];
__device__ __align__(16) float g_encS[16 * 2040 * 80];
__device__ __align__(16) float g_encQ[16 * 504 * 80];
__device__ unsigned g_gmax[32];
__device__ unsigned g_cnt[16];
__device__ unsigned g_ticket;
__device__ unsigned g_done[4][16];

// ---------------------------------------------------------------------------
// Weight prep (+ scheduler state reset)
// ---------------------------------------------------------------------------
__global__ void prep_kernel(const float* __restrict__ w_wide,
                            const float* __restrict__ w_1x1,
                            const float* __restrict__ w_f0,
                            const float* __restrict__ w_f1,
                            const float* __restrict__ emb) {
    int g = blockIdx.x * blockDim.x + threadIdx.x;
    int stride = gridDim.x * blockDim.x;
    for (int idx = g; idx < 4 * 160 * 320; idx += stride) {
        float v = w_wide[idx];
        __nv_bfloat16 h = __float2bfloat16(v);
        g_wbh[idx] = h;
        g_wbl[idx] = __float2bfloat16(v - __bfloat162float(h));
    }
    for (int idx = g; idx < 4 * 80 * 128; idx += stride) {
        int l = idx / 10240, r = idx % 10240;
        int oc = r >> 7, k = r & 127;
        float v = (k < 80) ? w_1x1[l * 6400 + oc * 80 + k] : 0.f;
        __nv_bfloat16 h = __float2bfloat16(v);
        __nv_bfloat16 lo = __float2bfloat16(v - __bfloat162float(h));
        uint32_t off = (uint32_t)(((oc >> 3) + (k >> 6) * 10) * 1024 + (oc & 7) * 128 + (k & 63) * 2);
        uint32_t sw  = off ^ ((off >> 3) & 0x70);
        *(__nv_bfloat16*)(g_w1s[l][0] + sw) = h;
        *(__nv_bfloat16*)(g_w1s[l][1] + sw) = lo;
    }
    for (int idx = g; idx < 80 * 128; idx += stride) {
        int oc = idx >> 7, k = idx & 127;
        uint32_t off = (uint32_t)(((oc >> 3) + (k >> 6) * 10) * 1024 + (oc & 7) * 128 + (k & 63) * 2);
        uint32_t sw  = off ^ ((off >> 3) & 0x70);
        float v0 = (k < 80) ? w_f0[oc * 80 + k] : 0.f;
        float v1 = (k < 80) ? w_f1[oc * 80 + k] : 0.f;
        __nv_bfloat16 h0 = __float2bfloat16(v0);
        __nv_bfloat16 h1 = __float2bfloat16(v1);
        *(__nv_bfloat16*)(g_wf0s[0] + sw) = h0;
        *(__nv_bfloat16*)(g_wf0s[1] + sw) = __float2bfloat16(v0 - __bfloat162float(h0));
        *(__nv_bfloat16*)(g_wf1s[0] + sw) = h1;
        *(__nv_bfloat16*)(g_wf1s[1] + sw) = __float2bfloat16(v1 - __bfloat162float(h1));
    }
    for (int idx = g; idx < 512 * 128; idx += stride) {
        int kc = idx >> 7;
        int k  = idx & 127;
        int ch = kc >> 6, r = kc & 63;
        float v = (k < 80) ? emb[kc * 80 + k] : 0.f;
        __nv_bfloat16 h = __float2bfloat16(v);
        uint32_t off = (uint32_t)(((r >> 3) + (k >> 6) * 8) * 1024 + (r & 7) * 128 + (k & 63) * 2);
        uint32_t sw  = off ^ ((off >> 3) & 0x70);
        *(__nv_bfloat16*)(g_embs[0][ch] + sw) = h;
        *(__nv_bfloat16*)(g_embs[1][ch] + sw) = __float2bfloat16(v - __bfloat162float(h));
    }
    for (int idx = g; idx < 4 * 80 * 80; idx += stride) {
        int ic = idx % 80, oc = (idx / 80) % 80, l = idx / 6400;
        g_w1t[l * 6400 + ic * 80 + oc] = w_1x1[idx];
    }
    for (int idx = g; idx < 6400; idx += stride) {
        int ic = idx % 80, oc = idx / 80;
        g_wf0t[ic * 80 + oc] = w_f0[idx];
        g_wf1t[ic * 80 + oc] = w_f1[idx];
    }
    for (int k = g; k < 512; k += stride) {
        float s = 0.f;
        for (int c = 0; c < 80; c++) { float v = emb[k * 80 + c]; s += v * v; }
        g_e2[k] = s;
    }
    if (g < 32) g_gmax[g] = 0u;
    if (g < 16) g_cnt[g] = 0u;
    if (g < 64) ((unsigned*)g_done)[g] = 0u;
    if (g == 64) g_ticket = 0u;
}

// ---------------------------------------------------------------------------
// smem layout (1024-aligned base)
// ---------------------------------------------------------------------------
#define OFF_A_HI  0
#define OFF_A_LO  16384
#define OFF_B_HI  32768
#define OFF_B_LO  53248
#define OFF2_A_HI 0
#define OFF2_A_LO 32768
#define OFF2_B_HI 65536
#define OFF2_B_LO 86016
#define VQ_B_HI   65536
#define VQ_B_LO   81920
#define SMEM_DYN  (1024 + 106496)

#define N_TICKETS 1856

#if HAS_TC
__device__ __forceinline__ void pack8(char* abp, int t, int g8, const float* v) {
    uint32_t ub[8]; float lo[8];
    #pragma unroll
    for (int i = 0; i < 8; i++) {
        ub[i] = __float_as_uint(v[i]);
        lo[i] = v[i] - __uint_as_float(ub[i] & 0xFFFF0000u);
    }
    uint4 hp, lp;
    hp.x = prmt_hi(ub[0], ub[1]); hp.y = prmt_hi(ub[2], ub[3]);
    hp.z = prmt_hi(ub[4], ub[5]); hp.w = prmt_hi(ub[6], ub[7]);
    lp.x = cvt_bf16x2(lo[1], lo[0]); lp.y = cvt_bf16x2(lo[3], lo[2]);
    lp.z = cvt_bf16x2(lo[5], lo[4]); lp.w = cvt_bf16x2(lo[7], lo[6]);
    uint32_t off = (uint32_t)(((t >> 3) + ((g8 >= 8) ? 16 : 0)) * 1024 + (t & 7) * 128 + (g8 & 7) * 16);
    uint32_t sw  = off ^ ((off >> 3) & 0x70);
    *(uint4*)(abp + OFF2_A_HI + sw) = hp;
    *(uint4*)(abp + OFF2_A_LO + sw) = lp;
}
// split/pack to precomputed swizzled address
__device__ __forceinline__ void pack8_sw(char* abp, uint32_t sw, const float* v) {
    uint32_t ub[8]; float lo[8];
    #pragma unroll
    for (int i = 0; i < 8; i++) {
        ub[i] = __float_as_uint(v[i]);
        lo[i] = v[i] - __uint_as_float(ub[i] & 0xFFFF0000u);
    }
    uint4 hp, lp;
    hp.x = prmt_hi(ub[0], ub[1]); hp.y = prmt_hi(ub[2], ub[3]);
    hp.z = prmt_hi(ub[4], ub[5]); hp.w = prmt_hi(ub[6], ub[7]);
    lp.x = cvt_bf16x2(lo[1], lo[0]); lp.y = cvt_bf16x2(lo[3], lo[2]);
    lp.z = cvt_bf16x2(lo[5], lo[4]); lp.w = cvt_bf16x2(lo[7], lo[6]);
    *(uint4*)(abp + OFF_A_HI + sw) = hp;
    *(uint4*)(abp + OFF_A_LO + sw) = lp;
}
// weight-image copy on warps 8-9 (threads 256..319)
__device__ __forceinline__ void copy_w2(char* abp, const char* hi, const char* lo, int tid) {
    if (tid >= 256) {
        for (int i = tid - 256; i < 1280; i += 64) {
            ((uint4*)(abp + OFF2_B_HI))[i] = __ldg((const uint4*)hi + i);
            ((uint4*)(abp + OFF2_B_LO))[i] = __ldg((const uint4*)lo + i);
        }
    }
}
__device__ __forceinline__ void issue_gemm2(uint32_t tmem_dst, uint32_t ab, uint32_t mbar) {
    u64 dAh = make_desc(ab + OFF2_A_HI), dAl = make_desc(ab + OFF2_A_LO);
    u64 dBh = make_desc(ab + OFF2_B_HI), dBl = make_desc(ab + OFF2_B_LO);
    u64 pA[3] = {dAh, dAh, dAl};
    u64 pB[3] = {dBh, dBl, dBh};
    #pragma unroll
    for (int p = 0; p < 3; p++) {
        #pragma unroll
        for (int s = 0; s < 5; s++) {
            uint32_t en = (p == 0 && s == 0) ? 0u : 1u;
            u64 ao = (s < 4) ? (u64)(2 * s) : 1024ull;
            u64 bo = (s < 4) ? (u64)(2 * s) : 640ull;
            mma_f16_ss(tmem_dst, pA[p] + ao, pB[p] + bo, IDESC_W, en);
        }
    }
    TCGEN05_COMMIT(mbar);
}
__device__ __forceinline__ void issue_gemmv(uint32_t tmem_dst, uint32_t ab, uint32_t mbar) {
    u64 dAh = make_desc(ab + OFF2_A_HI), dAl = make_desc(ab + OFF2_A_LO);
    u64 dBh = make_desc(ab + VQ_B_HI),  dBl = make_desc(ab + VQ_B_LO);
    u64 pA[3] = {dAh, dAh, dAl};
    u64 pB[3] = {dBh, dBl, dBh};
    #pragma unroll
    for (int p = 0; p < 3; p++) {
        #pragma unroll
        for (int s = 0; s < 5; s++) {
            uint32_t en = (p == 0 && s == 0) ? 0u : 1u;
            u64 ao = (s < 4) ? (u64)(2 * s) : 1024ull;
            u64 bo = (s < 4) ? (u64)(2 * s) : 512ull;
            mma_f16_ss(tmem_dst, pA[p] + ao, pB[p] + bo, IDESC_V, en);
        }
    }
    TCGEN05_COMMIT(mbar);
}
#endif

__device__ __forceinline__ unsigned fenc(float f) {
    unsigned u = __float_as_uint(f);
    return (u & 0x80000000u) ? ~u : (u | 0x80000000u);
}
__device__ __forceinline__ float fdec(unsigned e) {
    return (e & 0x80000000u) ? __uint_as_float(e ^ 0x80000000u)
                             : __uint_as_float(~e);
}

// ---------------------------------------------------------------------------
// Persistent mega-kernel, ordered-ticket scheduler; lean staging
// ---------------------------------------------------------------------------
__global__ __launch_bounds__(320, 2) void mega_kernel(
    const float* __restrict__ search, const float* __restrict__ query,
    float* __restrict__ A, float* __restrict__ Aq,
    float* __restrict__ B, float* __restrict__ Bq,
    float* __restrict__ eS, float* __restrict__ eQ,
    const __nv_bfloat16* __restrict__ wbh0, const __nv_bfloat16* __restrict__ wbl0,
    const float* __restrict__ b_wide, const float* __restrict__ b_1x1,
    const char* __restrict__ w1s,
    const char* __restrict__ wf0s, const char* __restrict__ wf1s,
    const float* __restrict__ bf0g, const float* __restrict__ bf1g,
    const float* __restrict__ emb, const float* __restrict__ wlin,
    const float* __restrict__ blin, float* __restrict__ out)
{
    extern __shared__ char dsm[];
    __shared__ float s_bias[400];
    __shared__ unsigned s_tk;
    __shared__ int s_lastl;
    __shared__ float se2[512];
    __shared__ float sdist[256];
    __shared__ int   sidx[256];
    __shared__ unsigned sm0, sm1;

    const int tid = threadIdx.x;
    const int wid = tid >> 5;
    uint32_t base_raw = smem_u32(dsm);
    uint32_t ab = (base_raw + 1023u) & ~1023u;
    char* abp = dsm + (ab - base_raw);

    for (int i = tid; i < 512; i += 320) se2[i] = __ldg(&g_e2[i]);
    if (tid == 0) s_lastl = -1;

#if HAS_TC
    __shared__ uint32_t s_tmem;
    __shared__ __align__(8) u64 s_mbar;
    if (tid == 0) MBARRIER_INIT(smem_u32(&s_mbar), 1);
    if (wid == 0) { TCGEN05_ALLOC(smem_u32(&s_tmem), 256); TCGEN05_RELINQ(); }
    __syncthreads();
    const uint32_t tmem = s_tmem;
    const uint32_t mbar = smem_u32(&s_mbar);

    // B-staging per-granule constants (fixed for whole kernel)
    uint32_t swB[4]; int baseB[4];
    #pragma unroll
    for (int r = 0; r < 4; r++) {
        int gi = r * 320 + tid;
        int row = gi >> 3, g8 = gi & 7;
        baseB[r] = row * 40 + g8;
        uint32_t off = (uint32_t)((row >> 3) * 1024 + (row & 7) * 128 + g8 * 16);
        swB[r] = off ^ ((off >> 3) & 0x70);
    }
#else
    __syncthreads();
#endif
    int mph = 0;
    (void)mph;

    while (true) {
        if (tid == 0) s_tk = atomicAdd(&g_ticket, 1u);
        __syncthreads();
        const unsigned tk = s_tk;
        if (tk >= N_TICKETS) break;

        if (tk < 1600) {
            // ================= layer tile =================
            int l, loc;
            if (tk < 640) { l = 0; loc = (int)tk; }
            else { l = 1 + (int)(tk - 640) / 320; loc = (int)(tk - 640) % 320; }
            const int tilesN = (l == 0) ? 40 : 20;
            const int n = loc / tilesN, idx = loc % tilesN;
            const int blocksS = (l == 0) ? 32 : 16;

            if (l > 0) {
                const unsigned need = (l == 1) ? 40u : 20u;
                if (tid == 0) {
                    while (atomicAdd(&g_done[l - 1][n], 0u) < need) __nanosleep(200);
                    __threadfence();
                }
                __syncthreads();
            }

            const int cS[4]       = {2, 2, 1, 1};
            const int cTinS[4]    = {8192, 4095, 2046, 2043};
            const int cTinLdS[4]  = {8192, 4096, 2048, 4096};
            const int cToutS[4]   = {4095, 2046, 2043, 2040};
            const int cToutLdS[4] = {4096, 2048, 4096, 2040};
            const int cTinQ[4]    = {2048, 1023, 510, 507};
            const int cTinLdQ[4]  = {2048, 1024, 512, 1024};
            const int cToutQ[4]   = {1023, 510, 507, 504};
            const int cToutLdQ[4] = {1024, 512, 1024, 504};

            const bool FIRST = (l == 0);
            const bool RESID = (l > 0);
            const bool FUSE  = (l == 3);
            const int  S     = cS[l];

            const float *xinS_, *xinQ_; float *xoutS_, *xoutQ_;
            switch (l) {
                case 0:  xinS_ = search; xinQ_ = query; xoutS_ = A;  xoutQ_ = Aq; break;
                case 1:  xinS_ = A;      xinQ_ = Aq;    xoutS_ = B;  xoutQ_ = Bq; break;
                case 2:  xinS_ = B;      xinQ_ = Bq;    xoutS_ = A;  xoutQ_ = Aq; break;
                default: xinS_ = A;      xinQ_ = Aq;    xoutS_ = eS; xoutQ_ = eQ; break;
            }
            const float* xin; float* xout; int Tin, TinLd, Tout, ToutLd, t0;
            if (idx < blocksS) {
                xin = xinS_; xout = xoutS_; Tin = cTinS[l]; TinLd = cTinLdS[l];
                Tout = cToutS[l]; ToutLd = cToutLdS[l]; t0 = idx * 128;
            } else {
                xin = xinQ_; xout = xoutQ_; Tin = cTinQ[l]; TinLd = cTinLdQ[l];
                Tout = cToutQ[l]; ToutLd = cToutLdQ[l]; t0 = (idx - blocksS) * 128;
            }
            const float* xin_n = xin + (size_t)n * 80 * TinLd;
            const __nv_bfloat16* wbh = wbh0 + l * 51200;
            const __nv_bfloat16* wbl = wbl0 + l * 51200;
            const char* w2h = w1s + (size_t)l * 2 * 20480;
            const char* w2l = w2h + 20480;

            if (s_lastl != l) {
                const float* bw = b_wide + l * 160;
                const float* b1 = b_1x1 + l * 80;
                for (int i = tid; i < 400; i += 320) {
                    float v = 0.f;
                    if (i < 160) v = __ldg(bw + i);
                    else if (i < 240) v = __ldg(b1 + i - 160);
                    else if (FUSE && i < 320) v = __ldg(bf0g + i - 240);
                    else if (FUSE) v = __ldg(bf1g + i - 320);
                    s_bias[i] = v;
                }
            }

#if HAS_TC
            // A-staging per-granule constants for this tile
            int tA[4], g8A[4]; uint32_t swA[4];
            #pragma unroll
            for (int r = 0; r < 4; r++) {
                int gi = r * 320 + tid;
                int t, g8;
                if (FIRST) { g8 = gi & 7; t = gi >> 3; }
                else       { t = gi & 127; g8 = gi >> 7; }
                tA[r] = t; g8A[r] = g8;
                uint32_t off = (uint32_t)((t >> 3) * 1024 + (t & 7) * 128 + g8 * 16);
                swA[r] = off ^ ((off >> 3) & 0x70);
            }
            const bool interior = (S * (t0 + 127) + 3) < Tin;

            auto stageA = [&](int r, int kc16) {
                const int t = tA[r], g8 = g8A[r];
                const int c0 = kc16 + g8 * 2;
                const int u0 = S * (t0 + t);
                float v[8];
                if (FIRST) {
                    const float* p0 = xin_n + (size_t)u0 * 80 + c0;
                    if (interior) {
                        #pragma unroll
                        for (int j = 0; j < 4; j++) {
                            float2 p = __ldg((const float2*)(p0 + (size_t)j * 80));
                            v[j] = p.x; v[4 + j] = p.y;
                        }
                    } else {
                        #pragma unroll
                        for (int j = 0; j < 4; j++) {
                            if (u0 + j < Tin) {
                                float2 p = __ldg((const float2*)(p0 + (size_t)j * 80));
                                v[j] = p.x; v[4 + j] = p.y;
                            } else { v[j] = 0.f; v[4 + j] = 0.f; }
                        }
                    }
                } else {
                    const float* r0 = xin_n + (size_t)c0 * TinLd + u0;
                    if (interior) {
                        #pragma unroll
                        for (int j = 0; j < 4; j++) {
                            v[j]     = __ldg(r0 + j);
                            v[4 + j] = __ldg(r0 + TinLd + j);
                        }
                    } else {
                        #pragma unroll
                        for (int j = 0; j < 4; j++) {
                            bool ok = (u0 + j) < Tin;
                            v[j]     = ok ? __ldg(r0 + j)         : 0.f;
                            v[4 + j] = ok ? __ldg(r0 + TinLd + j) : 0.f;
                        }
                    }
                }
                pack8_sw(abp, swA[r], v);
            };

            // ---- wide GEMM: 5 K-chunks of 64 -> tmem cols 0..159 ----
            for (int kc = 0; kc < 5; kc++) {
                if (kc > 0) { MBAR_WAIT(mbar, mph); mph ^= 1; }
                const int kc16 = kc * 16;
                stageA(0, kc16);
                stageA(1, kc16);
                stageA(2, kc16);
                if (tid < 64) stageA(3, kc16);
                {
                    const uint4* srcH = (const uint4*)wbh;
                    const uint4* srcL = (const uint4*)wbl;
                    const int so = kc << 3;
                    #pragma unroll
                    for (int r = 0; r < 4; r++) {
                        int si = baseB[r] + so;
                        *(uint4*)(abp + OFF_B_HI + swB[r]) = __ldg(srcH + si);
                        *(uint4*)(abp + OFF_B_LO + swB[r]) = __ldg(srcL + si);
                    }
                }
                FENCE_ASYNC_SHARED();
                __syncthreads();
                if (wid == 0 && elect_one()) {
                    u64 dAh = make_desc(ab + OFF_A_HI), dAl = make_desc(ab + OFF_A_LO);
                    u64 dBh = make_desc(ab + OFF_B_HI), dBl = make_desc(ab + OFF_B_LO);
                    u64 pA[3] = {dAh, dAh, dAl};
                    u64 pB[3] = {dBh, dBl, dBh};
                    #pragma unroll
                    for (int p = 0; p < 3; p++) {
                        #pragma unroll
                        for (int s = 0; s < 4; s++) {
                            uint32_t en = (kc == 0 && p == 0 && s == 0) ? 0u : 1u;
                            u64 ad = pA[p] + s * 2;
                            mma_f16_ss(tmem,      ad, pB[p] + s * 2,       IDESC_W, en);
                            mma_f16_ss(tmem + 80, ad, pB[p] + 640 + s * 2, IDESC_W, en);
                        }
                    }
                    TCGEN05_COMMIT(mbar);
                }
            }
            MBAR_WAIT(mbar, mph); mph ^= 1;

            // ---- gate -> bf16 A2: 8 warps ----
            if (tid < 256) {
                TCGEN05_FENCE_AFTER();
                const int t = tid & 127;
                const int half = tid >> 7;
                uint32_t da[32], dg[32];
                if (half == 0) {
                    #pragma unroll
                    for (int ch = 0; ch < 2; ch++) {
                        int a0 = ch * 32;
                        LDTM_X32(da, tmem + a0); LDTM_X32(dg, tmem + 80 + a0);
                        TCGEN05_WAIT_LD();
                        float gv[32];
                        for (int i = 0; i < 32; i++) {
                            float a = __uint_as_float(da[i]) + s_bias[a0 + i];
                            float g = __uint_as_float(dg[i]) + s_bias[80 + a0 + i];
                            gv[i] = gatef(a, g);
                        }
                        #pragma unroll
                        for (int q = 0; q < 4; q++)
                            pack8(abp, t, (a0 >> 3) + q, gv + q * 8);
                    }
                } else {
                    LDTM_X16(da, tmem + 64); LDTM_X16(dg, tmem + 144);
                    TCGEN05_WAIT_LD();
                    float gv[16];
                    for (int i = 0; i < 16; i++) {
                        float a = __uint_as_float(da[i]) + s_bias[64 + i];
                        float g = __uint_as_float(dg[i]) + s_bias[144 + i];
                        gv[i] = gatef(a, g);
                    }
                    pack8(abp, t, 8, gv);
                    pack8(abp, t, 9, gv + 8);
                }
            }
            copy_w2(abp, w2h, w2l, tid);
            FENCE_ASYNC_SHARED();
            __syncthreads();
            if (wid == 0 && elect_one()) issue_gemm2(tmem + 160, ab, mbar);
            MBAR_WAIT(mbar, mph); mph ^= 1;

            if (!FUSE) {
                if (tid < 256) {
                    TCGEN05_FENCE_AFTER();
                    const int t = tid & 127;
                    const int half = tid >> 7;
                    const bool tv = (t0 + t) < Tout;
                    uint32_t d[32];
                    if (half == 0) {
                        #pragma unroll
                        for (int ch = 0; ch < 2; ch++) {
                            int a0 = ch * 32;
                            LDTM_X32(d, tmem + 160 + a0);
                            TCGEN05_WAIT_LD();
                            if (tv) {
                                for (int i = 0; i < 32; i++) {
                                    int c = a0 + i;
                                    float v = __uint_as_float(d[i]) + s_bias[160 + c];
                                    if (RESID) v += __ldg(xin_n + (size_t)c * TinLd + S * (t0 + t) + 3);
                                    xout[((size_t)n * 80 + c) * ToutLd + t0 + t] = v;
                                }
                            }
                        }
                    } else {
                        LDTM_X16(d, tmem + 160 + 64);
                        TCGEN05_WAIT_LD();
                        if (tv) {
                            for (int i = 0; i < 16; i++) {
                                int c = 64 + i;
                                float v = __uint_as_float(d[i]) + s_bias[160 + c];
                                if (RESID) v += __ldg(xin_n + (size_t)c * TinLd + S * (t0 + t) + 3);
                                xout[((size_t)n * 80 + c) * ToutLd + t0 + t] = v;
                            }
                        }
                    }
                }
            } else {
                if (tid < 256) {
                    TCGEN05_FENCE_AFTER();
                    const int t = tid & 127;
                    const int half = tid >> 7;
                    const bool tv = (t0 + t) < Tout;
                    uint32_t d[32];
                    if (half == 0) {
                        #pragma unroll
                        for (int ch = 0; ch < 2; ch++) {
                            int a0 = ch * 32;
                            LDTM_X32(d, tmem + 160 + a0);
                            TCGEN05_WAIT_LD();
                            float v[32];
                            for (int i = 0; i < 32; i++) {
                                int c = a0 + i;
                                v[i] = __uint_as_float(d[i]) + s_bias[160 + c];
                                if (tv) v[i] += __ldg(xin_n + (size_t)c * TinLd + S * (t0 + t) + 3);
                            }
                            #pragma unroll
                            for (int q = 0; q < 4; q++)
                                pack8(abp, t, (a0 >> 3) + q, v + q * 8);
                        }
                    } else {
                        LDTM_X16(d, tmem + 160 + 64);
                        TCGEN05_WAIT_LD();
                        float v[16];
                        for (int i = 0; i < 16; i++) {
                            int c = 64 + i;
                            v[i] = __uint_as_float(d[i]) + s_bias[160 + c];
                            if (tv) v[i] += __ldg(xin_n + (size_t)c * TinLd + S * (t0 + t) + 3);
                        }
                        pack8(abp, t, 8, v);
                        pack8(abp, t, 9, v + 8);
                    }
                }
                copy_w2(abp, wf0s, wf0s + 20480, tid);
                FENCE_ASYNC_SHARED();
                __syncthreads();
                if (wid == 0 && elect_one()) issue_gemm2(tmem + 0, ab, mbar);
                MBAR_WAIT(mbar, mph); mph ^= 1;

                if (tid < 256) {
                    TCGEN05_FENCE_AFTER();
                    const int t = tid & 127;
                    const int half = tid >> 7;
                    uint32_t d[32];
                    if (half == 0) {
                        #pragma unroll
                        for (int ch = 0; ch < 2; ch++) {
                            int a0 = ch * 32;
                            LDTM_X32(d, tmem + a0);
                            TCGEN05_WAIT_LD();
                            float v[32];
                            for (int i = 0; i < 32; i++)
                                v[i] = fmaxf(__uint_as_float(d[i]) + s_bias[240 + a0 + i], 0.f);
                            #pragma unroll
                            for (int q = 0; q < 4; q++)
                                pack8(abp, t, (a0 >> 3) + q, v + q * 8);
                        }
                    } else {
                        LDTM_X16(d, tmem + 64);
                        TCGEN05_WAIT_LD();
                        float v[16];
                        for (int i = 0; i < 16; i++)
                            v[i] = fmaxf(__uint_as_float(d[i]) + s_bias[240 + 64 + i], 0.f);
                        pack8(abp, t, 8, v);
                        pack8(abp, t, 9, v + 8);
                    }
                }
                copy_w2(abp, wf1s, wf1s + 20480, tid);
                FENCE_ASYNC_SHARED();
                __syncthreads();
                if (wid == 0 && elect_one()) issue_gemm2(tmem + 80, ab, mbar);
                MBAR_WAIT(mbar, mph); mph ^= 1;

                if (tid < 256) {
                    TCGEN05_FENCE_AFTER();
                    const int t = tid & 127;
                    const int half = tid >> 7;
                    const bool tv = (t0 + t) < Tout;
                    uint32_t d[32];
                    if (half == 0) {
                        #pragma unroll
                        for (int ch = 0; ch < 2; ch++) {
                            int a0 = ch * 32;
                            LDTM_X32(d, tmem + 80 + a0);
                            TCGEN05_WAIT_LD();
                            if (tv) {
                                float* dst = xout + ((size_t)n * Tout + t0 + t) * 80 + a0;
                                for (int i = 0; i < 32; i += 4) {
                                    float4 o;
                                    o.x = __uint_as_float(d[i])     + s_bias[320 + a0 + i];
                                    o.y = __uint_as_float(d[i + 1]) + s_bias[320 + a0 + i + 1];
                                    o.z = __uint_as_float(d[i + 2]) + s_bias[320 + a0 + i + 2];
                                    o.w = __uint_as_float(d[i + 3]) + s_bias[320 + a0 + i + 3];
                                    *(float4*)(dst + i) = o;
                                }
                            }
                        }
                    } else {
                        LDTM_X16(d, tmem + 80 + 64);
                        TCGEN05_WAIT_LD();
                        if (tv) {
                            float* dst = xout + ((size_t)n * Tout + t0 + t) * 80 + 64;
                            for (int i = 0; i < 16; i += 4) {
                                float4 o;
                                o.x = __uint_as_float(d[i])     + s_bias[320 + 64 + i];
                                o.y = __uint_as_float(d[i + 1]) + s_bias[320 + 64 + i + 1];
                                o.z = __uint_as_float(d[i + 2]) + s_bias[320 + 64 + i + 2];
                                o.w = __uint_as_float(d[i + 3]) + s_bias[320 + 64 + i + 3];
                                *(float4*)(dst + i) = o;
                            }
                        }
                    }
                }
            }
#else
            // ------- safe scalar fallback (never runs on GB300) -------
            float* gsmF = (float*)(abp);
            float* bufF = (float*)(abp + 43008);
            __syncthreads();
            for (int e = tid; e < 80 * 128; e += 320) {
                int oc = e >> 7, tt = e & 127;
                float a = s_bias[oc], g = s_bias[oc + 80];
                for (int c = 0; c < 80; c++) {
                    for (int j = 0; j < 4; j++) {
                        int u = S * (t0 + tt) + j;
                        float xv = (u < Tin)
                                 ? (FIRST ? xin_n[(size_t)u * 80 + c]
                                          : xin_n[(size_t)c * TinLd + u]) : 0.f;
                        float wa = __bfloat162float(wbh[oc * 320 + c * 4 + j])
                                 + __bfloat162float(wbl[oc * 320 + c * 4 + j]);
                        float wg = __bfloat162float(wbh[(oc + 80) * 320 + c * 4 + j])
                                 + __bfloat162float(wbl[(oc + 80) * 320 + c * 4 + j]);
                        a = fmaf(wa, xv, a);
                        g = fmaf(wg, xv, g);
                    }
                }
                gsmF[oc * 132 + tt] = gatef(a, g);
            }
            __syncthreads();
            for (int e = tid; e < 80 * 128; e += 320) {
                int oc = e >> 7, tt = e & 127;
                int t = t0 + tt;
                float s = s_bias[160 + oc];
                for (int ic = 0; ic < 80; ic++)
                    s = fmaf(g_w1t[l * 6400 + ic * 80 + oc], gsmF[ic * 132 + tt], s);
                if (RESID && t < Tout) s += xin_n[(size_t)oc * TinLd + S * t + 3];
                if (FUSE) bufF[oc * 132 + tt] = s;
                else if (t < Tout) xout[((size_t)n * 80 + oc) * ToutLd + t] = s;
            }
            if (FUSE) {
                __syncthreads();
                for (int e = tid; e < 80 * 128; e += 320) {
                    int oc = e >> 7, tt = e & 127;
                    float s = s_bias[240 + oc];
                    for (int ic = 0; ic < 80; ic++)
                        s = fmaf(g_wf0t[ic * 80 + oc], bufF[ic * 132 + tt], s);
                    gsmF[oc * 132 + tt] = fmaxf(s, 0.f);
                }
                __syncthreads();
                for (int e = tid; e < 80 * 128; e += 320) {
                    int oc = e >> 7, tt = e & 127;
                    int t = t0 + tt;
                    if (t < Tout) {
                        float s = s_bias[320 + oc];
                        for (int ic = 0; ic < 80; ic++)
                            s = fmaf(g_wf1t[ic * 80 + oc], gsmF[ic * 132 + tt], s);
                        xout[((size_t)n * Tout + t) * 80 + oc] = s;
                    }
                }
            }
#endif
            __threadfence();
            __syncthreads();
            if (tid == 0) {
                atomicAdd(&g_done[l][n], 1u);
                s_lastl = l;
            }

        } else {
            // ================= VQ tile =================
            const int loc = (int)(tk - 1600);
            const int n = loc / 16, bxv = loc % 16;
            const int t0 = bxv * 128;

            if (tid == 0) {
                while (atomicAdd(&g_done[3][n], 0u) < 20u) __nanosleep(200);
                __threadfence();
                sm0 = 0u; sm1 = 0u;
            }
            __syncthreads();

#if HAS_TC
            {
                const float4* src = (const float4*)(eS + (size_t)n * 2040 * 80);
                const bool vint = (t0 + 127) < 2040;
                #pragma unroll
                for (int r = 0; r < 4; r++) {
                    int gi = r * 320 + tid;
                    int t = gi / 10, kg = gi % 10;
                    int tg = t0 + t;
                    float v[8] = {0.f, 0.f, 0.f, 0.f, 0.f, 0.f, 0.f, 0.f};
                    if (vint || tg < 2040) {
                        float4 a = __ldg(src + (size_t)tg * 20 + kg * 2);
                        float4 b = __ldg(src + (size_t)tg * 20 + kg * 2 + 1);
                        v[0] = a.x; v[1] = a.y; v[2] = a.z; v[3] = a.w;
                        v[4] = b.x; v[5] = b.y; v[6] = b.z; v[7] = b.w;
                    }
                    pack8(abp, t, kg, v);
                }
            }
            const int sub  = wid & 3;
            const int quar = wid >> 2;
            const int t    = sub * 32 + (tid & 31);
            float best = 3.4e38f;
            int   bi   = 0;

            for (int grp = 0; grp < 2; grp++) {
                for (int ch = 0; ch < 4; ch++) {
                    int cls = grp * 4 + ch;
                    #pragma unroll
                    for (int r = 0; r < 4; r++) {
                        int i = r * 320 + tid;
                        if (i < 1024) {
                            ((uint4*)(abp + VQ_B_HI))[i] = __ldg((const uint4*)(g_embs[0][cls]) + i);
                            ((uint4*)(abp + VQ_B_LO))[i] = __ldg((const uint4*)(g_embs[1][cls]) + i);
                        }
                    }
                    FENCE_ASYNC_SHARED();
                    __syncthreads();
                    if (wid == 0 && elect_one()) issue_gemmv(tmem + ch * 64, ab, mbar);
                    MBAR_WAIT(mbar, mph); mph ^= 1;
                }
                TCGEN05_FENCE_AFTER();
                if (wid < 8) {
                    uint32_t d[32];
                    #pragma unroll
                    for (int cc = 0; cc < 4; cc++) {
                        int c0 = quar * 128 + cc * 32;
                        LDTM_X32(d, tmem + c0);
                        TCGEN05_WAIT_LD();
                        for (int i = 0; i < 32; i++) {
                            int k = grp * 256 + c0 + i;
                            float dd = se2[k] - 2.f * __uint_as_float(d[i]);
                            if (dd < best) { best = dd; bi = k; }
                        }
                    }
                    TCGEN05_FENCE_BEFORE();
                }
                __syncthreads();
            }
            if (wid < 8) {
                sdist[t * 2 + quar] = best;
                sidx [t * 2 + quar] = bi;
            }
            __syncthreads();

            if (tid < 128) {
                float d0 = sdist[tid * 2],     d1 = sdist[tid * 2 + 1];
                int   i0 = sidx [tid * 2],     i1 = sidx [tid * 2 + 1];
                int bbi = (d1 < d0 || (d1 == d0 && i1 < i0)) ? i1 : i0;
                int tg2 = t0 + tid;
                if (tg2 < 2040) {
                    const float* dv = emb + (size_t)bbi * 80;
                    const float* qr = (tg2 < 2016)
                                    ? (eQ + ((size_t)n * 504 + (tg2 % 504)) * 80)
                                    : nullptr;
                    float s0 = blin[0], s1 = blin[1];
                    #pragma unroll 4
                    for (int c = 0; c < 80; c++) {
                        float v = dv[c] + (qr ? qr[c] : 0.f);
                        s0 = fmaf(v, wlin[c],      s0);
                        s1 = fmaf(v, wlin[80 + c], s1);
                    }
                    atomicMax(&sm0, fenc(tanhf(s0)));
                    atomicMax(&sm1, fenc(tanhf(s1)));
                }
            }
            __syncthreads();
#else
            __syncthreads();
            if (tid < 128) {
                int tg2 = t0 + tid;
                if (tg2 < 2040) {
                    const float* xr = eS + ((size_t)n * 2040 + tg2) * 80;
                    float best = 3.4e38f; int bbi = 0;
                    for (int k = 0; k < 512; k++) {
                        float dot = 0.f;
                        for (int c = 0; c < 80; c++) dot = fmaf(xr[c], emb[k * 80 + c], dot);
                        float dd = se2[k] - 2.f * dot;
                        if (dd < best) { best = dd; bbi = k; }
                    }
                    const float* dv = emb + (size_t)bbi * 80;
                    const float* qr = (tg2 < 2016)
                                    ? (eQ + ((size_t)n * 504 + (tg2 % 504)) * 80)
                                    : nullptr;
                    float s0 = blin[0], s1 = blin[1];
                    for (int c = 0; c < 80; c++) {
                        float v = dv[c] + (qr ? qr[c] : 0.f);
                        s0 = fmaf(v, wlin[c],      s0);
                        s1 = fmaf(v, wlin[80 + c], s1);
                    }
                    atomicMax(&sm0, fenc(tanhf(s0)));
                    atomicMax(&sm1, fenc(tanhf(s1)));
                }
            }
            __syncthreads();
#endif
            if (tid == 0) {
                atomicMax(&g_gmax[n * 2 + 0], sm0);
                atomicMax(&g_gmax[n * 2 + 1], sm1);
                __threadfence();
                unsigned old = atomicAdd(&g_cnt[n], 1u);
                if (old == 15u) {
                    unsigned e0 = atomicMax(&g_gmax[n * 2 + 0], 0u);
                    unsigned e1 = atomicMax(&g_gmax[n * 2 + 1], 0u);
                    out[n * 2 + 0] = fdec(e0);
                    out[n * 2 + 1] = fdec(e1);
                }
            }
        }
    }

#if HAS_TC
    __syncthreads();
    if (wid == 0) TCGEN05_DEALLOC(tmem, 256);
#endif
}

// ---------------------------------------------------------------------------
// Host launch
// ---------------------------------------------------------------------------
extern "C" void kernel_launch(void* const* d_in, const int* in_sizes, int n_in,
                              void* d_out, int out_size) {
    const float* search = (const float*)d_in[0];
    const float* query  = (const float*)d_in[1];
    const float* w_wide = (const float*)d_in[2];
    const float* b_wide = (const float*)d_in[3];
    const float* w_1x1  = (const float*)d_in[4];
    const float* b_1x1  = (const float*)d_in[5];
    const float* w_f0   = (const float*)d_in[6];
    const float* b_f0   = (const float*)d_in[7];
    const float* w_f1   = (const float*)d_in[8];
    const float* b_f1   = (const float*)d_in[9];
    const float* emb    = (const float*)d_in[10];
    const float* w_lin  = (const float*)d_in[11];
    const float* b_lin  = (const float*)d_in[12];
    float* out = (float*)d_out;

    void *pA, *pB, *pAq, *pBq, *pS, *pQ, *pwh, *pwl, *pw1s, *pwf0s, *pwf1s;
    cudaGetSymbolAddress(&pA,   g_bufA);
    cudaGetSymbolAddress(&pB,   g_bufB);
    cudaGetSymbolAddress(&pAq,  g_bufAq);
    cudaGetSymbolAddress(&pBq,  g_bufBq);
    cudaGetSymbolAddress(&pS,   g_encS);
    cudaGetSymbolAddress(&pQ,   g_encQ);
    cudaGetSymbolAddress(&pwh,  g_wbh);
    cudaGetSymbolAddress(&pwl,  g_wbl);
    cudaGetSymbolAddress(&pw1s, g_w1s);
    cudaGetSymbolAddress(&pwf0s, g_wf0s);
    cudaGetSymbolAddress(&pwf1s, g_wf1s);
    float* A   = (float*)pA;
    float* B   = (float*)pB;
    float* Aq  = (float*)pAq;
    float* Bq  = (float*)pBq;
    float* eS  = (float*)pS;
    float* eQ  = (float*)pQ;
    __nv_bfloat16* wbh = (__nv_bfloat16*)pwh;
    __nv_bfloat16* wbl = (__nv_bfloat16*)pwl;
    const char* w1s  = (const char*)pw1s;
    const char* wf0s = (const char*)pwf0s;
    const char* wf1s = (const char*)pwf1s;

    cudaFuncSetAttribute(mega_kernel,
                         cudaFuncAttributeMaxDynamicSharedMemorySize, SMEM_DYN);

    prep_kernel<<<80, 256>>>(w_wide, w_1x1, w_f0, w_f1, emb);

    mega_kernel<<<296, 320, SMEM_DYN>>>(
        search, query, A, Aq, B, Bq, eS, eQ,
        wbh, wbl, b_wide, b_1x1,
        w1s, wf0s, wf1s, b_f0, b_f1,
        emb, w_lin, b_lin, out);
}

// round 17
// speedup vs baseline: 1.0860x; 1.0860x over previous
#include <cuda_runtime.h>
#include <cuda_bf16.h>
#include <cstdint>

#define NB 16
typedef unsigned long long u64;

#if defined(__CUDA_ARCH_FEAT_SM103_ALL) || defined(__CUDA_ARCH_FEAT_SM100_ALL) || \
    (defined(__CUDA_ARCH_SPECIFIC__) && (__CUDA_ARCH_SPECIFIC__ >= 1000))
#define HAS_TC 1
#else
#define HAS_TC 0
#endif

// ---------------------------------------------------------------------------
// PTX helpers
// ---------------------------------------------------------------------------
__device__ __forceinline__ uint32_t smem_u32(const void* p) {
    uint32_t a;
    asm("{ .reg .u64 t; cvta.to.shared.u64 t, %1; cvt.u32.u64 %0, t; }" : "=r"(a) : "l"(p));
    return a;
}
__device__ __forceinline__ float ex2f(float x) {
    float r; asm("ex2.approx.f32 %0, %1;" : "=f"(r) : "f"(x)); return r;
}
__device__ __forceinline__ float rcpf(float x) {
    float r; asm("rcp.approx.f32 %0, %1;" : "=f"(r) : "f"(x)); return r;
}
__device__ __forceinline__ uint32_t prmt_hi(uint32_t a, uint32_t b) {
    uint32_t r; asm("prmt.b32 %0, %1, %2, 0x7632;" : "=r"(r) : "r"(a), "r"(b)); return r;
}
__device__ __forceinline__ uint32_t cvt_bf16x2(float hi, float lo) {
    uint32_t r; asm("cvt.rn.bf16x2.f32 %0, %1, %2;" : "=r"(r) : "f"(hi), "f"(lo)); return r;
}
__device__ __forceinline__ float gatef(float a, float g) {
    float e1 = ex2f(fminf(a * -2.885390082f, 80.f));
    float e2 = ex2f(fminf(g * -1.442695041f, 80.f));
    float r  = rcpf((1.f + e1) * (1.f + e2));
    return (1.f - e1) * r;
}

#define CP_ASYNC16(dst, src) \
    asm volatile("cp.async.cg.shared.global [%0], [%1], 16;" \
                 :: "r"((uint32_t)(dst)), "l"(src) : "memory")
#define CP_COMMIT() asm volatile("cp.async.commit_group;" ::: "memory")
#define CP_WAIT0()  asm volatile("cp.async.wait_group 0;" ::: "memory")

#if HAS_TC
__device__ __forceinline__ uint32_t elect_one() {
    uint32_t p;
    asm volatile("{\n\t.reg .pred p;\n\telect.sync _|p, 0xFFFFFFFF;\n\tselp.b32 %0, 1, 0, p;\n\t}" : "=r"(p));
    return p;
}

#define TCGEN05_ALLOC(sm, n) \
    asm volatile("tcgen05.alloc.cta_group::1.sync.aligned.shared::cta.b32 [%0], %1;" \
                 :: "r"((uint32_t)(sm)), "r"((uint32_t)(n)) : "memory")
#define TCGEN05_RELINQ() \
    asm volatile("tcgen05.relinquish_alloc_permit.cta_group::1.sync.aligned;")
#define TCGEN05_DEALLOC(t, n) \
    asm volatile("tcgen05.dealloc.cta_group::1.sync.aligned.b32 %0, %1;" :: "r"(t), "r"((uint32_t)(n)))
#define TCGEN05_COMMIT(mb) \
    asm volatile("tcgen05.commit.cta_group::1.mbarrier::arrive::one.shared::cluster.b64 [%0];" \
                 :: "r"((uint32_t)(mb)) : "memory")
#define TCGEN05_FENCE_AFTER()  asm volatile("tcgen05.fence::after_thread_sync;" ::: "memory")
#define TCGEN05_FENCE_BEFORE() asm volatile("tcgen05.fence::before_thread_sync;" ::: "memory")
#define TCGEN05_WAIT_LD()      asm volatile("tcgen05.wait::ld.sync.aligned;" ::: "memory")
#define FENCE_ASYNC_SHARED()   asm volatile("fence.proxy.async.shared::cta;" ::: "memory")
#define MBARRIER_INIT(mb, c) \
    asm volatile("mbarrier.init.shared.b64 [%0], %1;" :: "r"((uint32_t)(mb)), "r"((uint32_t)(c)) : "memory")

#define MBAR_WAIT(mb, ph) do {                                                  \
    uint32_t _m = (uint32_t)(mb), _p = (uint32_t)(ph), _d;                      \
    asm volatile("{\n\t.reg .pred p;\n\t"                                       \
        "mbarrier.try_wait.parity.acquire.cta.shared::cta.b64 p, [%1], %2;\n\t" \
        "selp.b32 %0, 1, 0, p;\n\t}" : "=r"(_d) : "r"(_m), "r"(_p) : "memory"); \
    if (!_d) {                                                                  \
        asm volatile("{\n\t.reg .pred P1;\n\t"                                  \
            "WL_%=:\n\t"                                                        \
            "mbarrier.try_wait.parity.acquire.cta.shared::cta.b64 P1, [%0], %1, 0x989680;\n\t" \
            "@P1 bra.uni WD_%=;\n\t"                                            \
            "bra.uni WL_%=;\n\t"                                                \
            "WD_%=:\n\t}" :: "r"(_m), "r"(_p) : "memory");                      \
    }                                                                           \
} while (0)

#define LDTM_X32(r, a) \
    asm volatile("tcgen05.ld.sync.aligned.32x32b.x32.b32 " \
        "{%0,%1,%2,%3,%4,%5,%6,%7,%8,%9,%10,%11,%12,%13,%14,%15," \
        "%16,%17,%18,%19,%20,%21,%22,%23,%24,%25,%26,%27,%28,%29,%30,%31}, [%32];" \
        : "=r"((r)[0]),"=r"((r)[1]),"=r"((r)[2]),"=r"((r)[3]),"=r"((r)[4]),"=r"((r)[5]),"=r"((r)[6]),"=r"((r)[7]), \
          "=r"((r)[8]),"=r"((r)[9]),"=r"((r)[10]),"=r"((r)[11]),"=r"((r)[12]),"=r"((r)[13]),"=r"((r)[14]),"=r"((r)[15]), \
          "=r"((r)[16]),"=r"((r)[17]),"=r"((r)[18]),"=r"((r)[19]),"=r"((r)[20]),"=r"((r)[21]),"=r"((r)[22]),"=r"((r)[23]), \
          "=r"((r)[24]),"=r"((r)[25]),"=r"((r)[26]),"=r"((r)[27]),"=r"((r)[28]),"=r"((r)[29]),"=r"((r)[30]),"=r"((r)[31]) \
        : "r"(a))

#define LDTM_X16(r, a) \
    asm volatile("tcgen05.ld.sync.aligned.32x32b.x16.b32 " \
        "{%0,%1,%2,%3,%4,%5,%6,%7,%8,%9,%10,%11,%12,%13,%14,%15}, [%16];" \
        : "=r"((r)[0]),"=r"((r)[1]),"=r"((r)[2]),"=r"((r)[3]),"=r"((r)[4]),"=r"((r)[5]),"=r"((r)[6]),"=r"((r)[7]), \
          "=r"((r)[8]),"=r"((r)[9]),"=r"((r)[10]),"=r"((r)[11]),"=r"((r)[12]),"=r"((r)[13]),"=r"((r)[14]),"=r"((r)[15]) \
        : "r"(a))

__device__ __forceinline__ void mma_f16_ss(uint32_t d, u64 ad, u64 bd, uint32_t idesc, uint32_t en) {
    asm volatile("{\n\t.reg .pred p;\n\tsetp.ne.u32 p, %5, 0;\n\t"
        "tcgen05.mma.cta_group::1.kind::f16 [%0], %1, %2, %3, {%4,%4,%4,%4}, p;\n\t}"
        :: "r"(d), "l"(ad), "l"(bd), "r"(idesc), "r"(0u), "r"(en) : "memory");
}

static __device__ __forceinline__ u64 make_desc(uint32_t addr) {
    return (u64(2) << 61) | (u64(1) << 46) | (u64(64) << 32) | (u64(1) << 16)
         | ((u64)(addr >> 4) & 0x3FFF);
}

#define IDESC_W ((1u<<4) | (1u<<7) | (1u<<10) | (10u<<17) | (8u<<24))
#define IDESC_V ((1u<<4) | (1u<<7) | (1u<<10) | (8u<<17)  | (8u<<24))
#endif // HAS_TC

// ---------------------------------------------------------------------------
// Device scratch
// ---------------------------------------------------------------------------
__device__ __align__(16) __nv_bfloat16 g_wbh[4 * 160 * 320];
__device__ __align__(16) __nv_bfloat16 g_wbl[4 * 160 * 320];
__device__ __align__(16) char g_w1s [4][2][20480];
__device__ __align__(16) char g_wf0s[2][20480];
__device__ __align__(16) char g_wf1s[2][20480];
__device__ __align__(16) char g_embs[2][8][16384];
__device__ __align__(16) float g_w1t [4 * 80 * 80];
__device__ __align__(16) float g_wf0t[80 * 80];
__device__ __align__(16) float g_wf1t[80 * 80];
__device__ __align__(16) float g_e2  [512];
__device__ __align__(16) float g_bufA [16 * 80 * 4096];
__device__ __align__(16) float g_bufB [16 * 80 * 2048];
__device__ __align__(16) float g_bufAq[16 * 80 * 1024];
__device__ __align__(16) float g_bufBq[16 * 80 * 512];
__device__ __align__(16) float g_encS[16 * 2040 * 80];
__device__ __align__(16) float g_encQ[16 * 504 * 80];
__device__ unsigned g_gmax[32];
__device__ unsigned g_cnt[16];
__device__ unsigned g_ticket;
__device__ unsigned g_done[4][16];

// ---------------------------------------------------------------------------
// Weight prep (+ scheduler state reset)
// ---------------------------------------------------------------------------
__global__ void prep_kernel(const float* __restrict__ w_wide,
                            const float* __restrict__ w_1x1,
                            const float* __restrict__ w_f0,
                            const float* __restrict__ w_f1,
                            const float* __restrict__ emb) {
    int g = blockIdx.x * blockDim.x + threadIdx.x;
    int stride = gridDim.x * blockDim.x;
    for (int idx = g; idx < 4 * 160 * 320; idx += stride) {
        float v = w_wide[idx];
        __nv_bfloat16 h = __float2bfloat16(v);
        g_wbh[idx] = h;
        g_wbl[idx] = __float2bfloat16(v - __bfloat162float(h));
    }
    for (int idx = g; idx < 4 * 80 * 128; idx += stride) {
        int l = idx / 10240, r = idx % 10240;
        int oc = r >> 7, k = r & 127;
        float v = (k < 80) ? w_1x1[l * 6400 + oc * 80 + k] : 0.f;
        __nv_bfloat16 h = __float2bfloat16(v);
        __nv_bfloat16 lo = __float2bfloat16(v - __bfloat162float(h));
        uint32_t off = (uint32_t)(((oc >> 3) + (k >> 6) * 10) * 1024 + (oc & 7) * 128 + (k & 63) * 2);
        uint32_t sw  = off ^ ((off >> 3) & 0x70);
        *(__nv_bfloat16*)(g_w1s[l][0] + sw) = h;
        *(__nv_bfloat16*)(g_w1s[l][1] + sw) = lo;
    }
    for (int idx = g; idx < 80 * 128; idx += stride) {
        int oc = idx >> 7, k = idx & 127;
        uint32_t off = (uint32_t)(((oc >> 3) + (k >> 6) * 10) * 1024 + (oc & 7) * 128 + (k & 63) * 2);
        uint32_t sw  = off ^ ((off >> 3) & 0x70);
        float v0 = (k < 80) ? w_f0[oc * 80 + k] : 0.f;
        float v1 = (k < 80) ? w_f1[oc * 80 + k] : 0.f;
        __nv_bfloat16 h0 = __float2bfloat16(v0);
        __nv_bfloat16 h1 = __float2bfloat16(v1);
        *(__nv_bfloat16*)(g_wf0s[0] + sw) = h0;
        *(__nv_bfloat16*)(g_wf0s[1] + sw) = __float2bfloat16(v0 - __bfloat162float(h0));
        *(__nv_bfloat16*)(g_wf1s[0] + sw) = h1;
        *(__nv_bfloat16*)(g_wf1s[1] + sw) = __float2bfloat16(v1 - __bfloat162float(h1));
    }
    for (int idx = g; idx < 512 * 128; idx += stride) {
        int kc = idx >> 7;
        int k  = idx & 127;
        int ch = kc >> 6, r = kc & 63;
        float v = (k < 80) ? emb[kc * 80 + k] : 0.f;
        __nv_bfloat16 h = __float2bfloat16(v);
        uint32_t off = (uint32_t)(((r >> 3) + (k >> 6) * 8) * 1024 + (r & 7) * 128 + (k & 63) * 2);
        uint32_t sw  = off ^ ((off >> 3) & 0x70);
        *(__nv_bfloat16*)(g_embs[0][ch] + sw) = h;
        *(__nv_bfloat16*)(g_embs[1][ch] + sw) = __float2bfloat16(v - __bfloat162float(h));
    }
    for (int idx = g; idx < 4 * 80 * 80; idx += stride) {
        int ic = idx % 80, oc = (idx / 80) % 80, l = idx / 6400;
        g_w1t[l * 6400 + ic * 80 + oc] = w_1x1[idx];
    }
    for (int idx = g; idx < 6400; idx += stride) {
        int ic = idx % 80, oc = idx / 80;
        g_wf0t[ic * 80 + oc] = w_f0[idx];
        g_wf1t[ic * 80 + oc] = w_f1[idx];
    }
    for (int k = g; k < 512; k += stride) {
        float s = 0.f;
        for (int c = 0; c < 80; c++) { float v = emb[k * 80 + c]; s += v * v; }
        g_e2[k] = s;
    }
    if (g < 32) g_gmax[g] = 0u;
    if (g < 16) g_cnt[g] = 0u;
    if (g < 64) ((unsigned*)g_done)[g] = 0u;
    if (g == 64) g_ticket = 0u;
}

// ---------------------------------------------------------------------------
// smem layout (1024-aligned base)
// ---------------------------------------------------------------------------
#define OFF_A_HI  0
#define OFF_A_LO  16384
#define OFF_B_HI  32768
#define OFF_B_LO  53248
#define OFF2_A_HI 0
#define OFF2_A_LO 32768
#define OFF2_B_HI 65536
#define OFF2_B_LO 86016
#define VQ_B_HI   65536
#define VQ_B_LO   81920
#define SMEM_DYN  (1024 + 106496)

#define N_TICKETS 1856

#if HAS_TC
__device__ __forceinline__ void pack8(char* abp, int t, int g8, const float* v) {
    uint32_t ub[8]; float lo[8];
    #pragma unroll
    for (int i = 0; i < 8; i++) {
        ub[i] = __float_as_uint(v[i]);
        lo[i] = v[i] - __uint_as_float(ub[i] & 0xFFFF0000u);
    }
    uint4 hp, lp;
    hp.x = prmt_hi(ub[0], ub[1]); hp.y = prmt_hi(ub[2], ub[3]);
    hp.z = prmt_hi(ub[4], ub[5]); hp.w = prmt_hi(ub[6], ub[7]);
    lp.x = cvt_bf16x2(lo[1], lo[0]); lp.y = cvt_bf16x2(lo[3], lo[2]);
    lp.z = cvt_bf16x2(lo[5], lo[4]); lp.w = cvt_bf16x2(lo[7], lo[6]);
    uint32_t off = (uint32_t)(((t >> 3) + ((g8 >= 8) ? 16 : 0)) * 1024 + (t & 7) * 128 + (g8 & 7) * 16);
    uint32_t sw  = off ^ ((off >> 3) & 0x70);
    *(uint4*)(abp + OFF2_A_HI + sw) = hp;
    *(uint4*)(abp + OFF2_A_LO + sw) = lp;
}
// weight-image copy on threads 128..319 via cp.async (fire-and-forget)
__device__ __forceinline__ void copy_w2(uint32_t ab, const char* hi, const char* lo, int tid) {
    if (tid >= 128) {
        for (int i = tid - 128; i < 1280; i += 192) {
            CP_ASYNC16(ab + OFF2_B_HI + i * 16, hi + (size_t)i * 16);
            CP_ASYNC16(ab + OFF2_B_LO + i * 16, lo + (size_t)i * 16);
        }
        CP_COMMIT();
    }
}
__device__ __forceinline__ void issue_gemm2(uint32_t tmem_dst, uint32_t ab, uint32_t mbar) {
    u64 dAh = make_desc(ab + OFF2_A_HI), dAl = make_desc(ab + OFF2_A_LO);
    u64 dBh = make_desc(ab + OFF2_B_HI), dBl = make_desc(ab + OFF2_B_LO);
    u64 pA[3] = {dAh, dAh, dAl};
    u64 pB[3] = {dBh, dBl, dBh};
    #pragma unroll
    for (int p = 0; p < 3; p++) {
        #pragma unroll
        for (int s = 0; s < 5; s++) {
            uint32_t en = (p == 0 && s == 0) ? 0u : 1u;
            u64 ao = (s < 4) ? (u64)(2 * s) : 1024ull;
            u64 bo = (s < 4) ? (u64)(2 * s) : 640ull;
            mma_f16_ss(tmem_dst, pA[p] + ao, pB[p] + bo, IDESC_W, en);
        }
    }
    TCGEN05_COMMIT(mbar);
}
__device__ __forceinline__ void issue_gemmv(uint32_t tmem_dst, uint32_t ab, uint32_t mbar) {
    u64 dAh = make_desc(ab + OFF2_A_HI), dAl = make_desc(ab + OFF2_A_LO);
    u64 dBh = make_desc(ab + VQ_B_HI),  dBl = make_desc(ab + VQ_B_LO);
    u64 pA[3] = {dAh, dAh, dAl};
    u64 pB[3] = {dBh, dBl, dBh};
    #pragma unroll
    for (int p = 0; p < 3; p++) {
        #pragma unroll
        for (int s = 0; s < 5; s++) {
            uint32_t en = (p == 0 && s == 0) ? 0u : 1u;
            u64 ao = (s < 4) ? (u64)(2 * s) : 1024ull;
            u64 bo = (s < 4) ? (u64)(2 * s) : 512ull;
            mma_f16_ss(tmem_dst, pA[p] + ao, pB[p] + bo, IDESC_V, en);
        }
    }
    TCGEN05_COMMIT(mbar);
}
#endif

__device__ __forceinline__ unsigned fenc(float f) {
    unsigned u = __float_as_uint(f);
    return (u & 0x80000000u) ? ~u : (u | 0x80000000u);
}
__device__ __forceinline__ float fdec(unsigned e) {
    return (e & 0x80000000u) ? __uint_as_float(e ^ 0x80000000u)
                             : __uint_as_float(~e);
}

// ---------------------------------------------------------------------------
// Persistent mega-kernel, ordered-ticket scheduler; cp.async-overlapped staging
// ---------------------------------------------------------------------------
__global__ __launch_bounds__(320, 2) void mega_kernel(
    const float* __restrict__ search, const float* __restrict__ query,
    float* __restrict__ A, float* __restrict__ Aq,
    float* __restrict__ B, float* __restrict__ Bq,
    float* __restrict__ eS, float* __restrict__ eQ,
    const __nv_bfloat16* __restrict__ wbh0, const __nv_bfloat16* __restrict__ wbl0,
    const float* __restrict__ b_wide, const float* __restrict__ b_1x1,
    const char* __restrict__ w1s,
    const char* __restrict__ wf0s, const char* __restrict__ wf1s,
    const float* __restrict__ bf0g, const float* __restrict__ bf1g,
    const float* __restrict__ emb, const float* __restrict__ wlin,
    const float* __restrict__ blin, float* __restrict__ out)
{
    extern __shared__ char dsm[];
    __shared__ float s_bias[400];
    __shared__ unsigned s_tk;
    __shared__ float se2[512];
    __shared__ float sdist[256];
    __shared__ int   sidx[256];
    __shared__ unsigned sm0, sm1;

    const int tid = threadIdx.x;
    const int wid = tid >> 5;
    uint32_t base_raw = smem_u32(dsm);
    uint32_t ab = (base_raw + 1023u) & ~1023u;
    char* abp = dsm + (ab - base_raw);

    for (int i = tid; i < 512; i += 320) se2[i] = __ldg(&g_e2[i]);

#if HAS_TC
    __shared__ uint32_t s_tmem;
    __shared__ __align__(8) u64 s_mbar;
    if (tid == 0) MBARRIER_INIT(smem_u32(&s_mbar), 1);
    if (wid == 0) { TCGEN05_ALLOC(smem_u32(&s_tmem), 256); TCGEN05_RELINQ(); }
    __syncthreads();
    const uint32_t tmem = s_tmem;
    const uint32_t mbar = smem_u32(&s_mbar);
#else
    __syncthreads();
#endif
    int mph = 0;
    (void)mph;

    while (true) {
        if (tid == 0) s_tk = atomicAdd(&g_ticket, 1u);
        __syncthreads();
        const unsigned tk = s_tk;
        if (tk >= N_TICKETS) break;

        if (tk < 1600) {
            // ================= layer tile =================
            int l, loc;
            if (tk < 640) { l = 0; loc = (int)tk; }
            else { l = 1 + (int)(tk - 640) / 320; loc = (int)(tk - 640) % 320; }
            const int tilesN = (l == 0) ? 40 : 20;
            const int n = loc / tilesN, idx = loc % tilesN;
            const int blocksS = (l == 0) ? 32 : 16;

            if (l > 0) {
                const unsigned need = (l == 1) ? 40u : 20u;
                if (tid == 0) {
                    while (atomicAdd(&g_done[l - 1][n], 0u) < need) __nanosleep(200);
                    __threadfence();
                }
                __syncthreads();
            }

            const int cS[4]       = {2, 2, 1, 1};
            const int cTinS[4]    = {8192, 4095, 2046, 2043};
            const int cTinLdS[4]  = {8192, 4096, 2048, 4096};
            const int cToutS[4]   = {4095, 2046, 2043, 2040};
            const int cToutLdS[4] = {4096, 2048, 4096, 2040};
            const int cTinQ[4]    = {2048, 1023, 510, 507};
            const int cTinLdQ[4]  = {2048, 1024, 512, 1024};
            const int cToutQ[4]   = {1023, 510, 507, 504};
            const int cToutLdQ[4] = {1024, 512, 1024, 504};

            const bool FIRST = (l == 0);
            const bool RESID = (l > 0);
            const bool FUSE  = (l == 3);
            const int  S     = cS[l];

            const float *xinS_, *xinQ_; float *xoutS_, *xoutQ_;
            switch (l) {
                case 0:  xinS_ = search; xinQ_ = query; xoutS_ = A;  xoutQ_ = Aq; break;
                case 1:  xinS_ = A;      xinQ_ = Aq;    xoutS_ = B;  xoutQ_ = Bq; break;
                case 2:  xinS_ = B;      xinQ_ = Bq;    xoutS_ = A;  xoutQ_ = Aq; break;
                default: xinS_ = A;      xinQ_ = Aq;    xoutS_ = eS; xoutQ_ = eQ; break;
            }
            const float* xin; float* xout; int Tin, TinLd, Tout, ToutLd, t0;
            if (idx < blocksS) {
                xin = xinS_; xout = xoutS_; Tin = cTinS[l]; TinLd = cTinLdS[l];
                Tout = cToutS[l]; ToutLd = cToutLdS[l]; t0 = idx * 128;
            } else {
                xin = xinQ_; xout = xoutQ_; Tin = cTinQ[l]; TinLd = cTinLdQ[l];
                Tout = cToutQ[l]; ToutLd = cToutLdQ[l]; t0 = (idx - blocksS) * 128;
            }
            const float* xin_n = xin + (size_t)n * 80 * TinLd;
            const __nv_bfloat16* wbh = wbh0 + l * 51200;
            const __nv_bfloat16* wbl = wbl0 + l * 51200;
            const float* bw = b_wide + l * 160;
            const float* b1 = b_1x1 + l * 80;
            const char* w2h = w1s + (size_t)l * 2 * 20480;
            const char* w2l = w2h + 20480;

            for (int i = tid; i < 400; i += 320) {
                float v = 0.f;
                if (i < 160) v = __ldg(bw + i);
                else if (i < 240) v = __ldg(b1 + i - 160);
                else if (FUSE && i < 320) v = __ldg(bf0g + i - 240);
                else if (FUSE) v = __ldg(bf1g + i - 320);
                s_bias[i] = v;
            }

#if HAS_TC
            // ---- wide GEMM: 5 K-chunks of 64 -> tmem cols 0..159 ----
            for (int kc = 0; kc < 5; kc++) {
                if (kc > 0) { MBAR_WAIT(mbar, mph); mph ^= 1; }
                const int k0 = kc * 64;
                // stage B first via cp.async (latency overlaps A-pack below)
                {
                    const char* srcH = (const char*)wbh;
                    const char* srcL = (const char*)wbl;
                    #pragma unroll
                    for (int r = 0; r < 4; r++) {
                        int gi = r * 320 + tid;
                        int row = gi >> 3, g8 = gi & 7;
                        int si  = row * 40 + (kc << 3) + g8;
                        uint32_t off = (uint32_t)((row >> 3) * 1024 + (row & 7) * 128 + g8 * 16);
                        uint32_t sw  = off ^ ((off >> 3) & 0x70);
                        CP_ASYNC16(ab + OFF_B_HI + sw, srcH + (size_t)si * 16);
                        CP_ASYNC16(ab + OFF_B_LO + sw, srcL + (size_t)si * 16);
                    }
                    CP_COMMIT();
                }
                // stage A (im2col, hi/lo trunc split)
                for (int gi = tid; gi < 1024; gi += 320) {
                    int t, g8;
                    if (FIRST) { g8 = gi & 7; t = gi >> 3; }
                    else       { t = gi & 127; g8 = gi >> 7; }
                    int c0 = (k0 >> 2) + g8 * 2;
                    int u0 = S * (t0 + t);
                    float v[8];
                    if (FIRST) {
                        #pragma unroll
                        for (int j = 0; j < 4; j++) {
                            int u = u0 + j;
                            if (u < Tin) {
                                float2 p = __ldg((const float2*)&xin_n[(size_t)u * 80 + c0]);
                                v[j] = p.x; v[4 + j] = p.y;
                            } else { v[j] = 0.f; v[4 + j] = 0.f; }
                        }
                    } else {
                        const float* r0 = xin_n + (size_t)c0 * TinLd + u0;
                        #pragma unroll
                        for (int j = 0; j < 4; j++) {
                            bool ok = (u0 + j) < Tin;
                            v[j]     = ok ? __ldg(r0 + j)         : 0.f;
                            v[4 + j] = ok ? __ldg(r0 + TinLd + j) : 0.f;
                        }
                    }
                    uint32_t ub[8]; float lo[8];
                    #pragma unroll
                    for (int i = 0; i < 8; i++) {
                        ub[i] = __float_as_uint(v[i]);
                        lo[i] = v[i] - __uint_as_float(ub[i] & 0xFFFF0000u);
                    }
                    uint4 hp, lp;
                    hp.x = prmt_hi(ub[0], ub[1]); hp.y = prmt_hi(ub[2], ub[3]);
                    hp.z = prmt_hi(ub[4], ub[5]); hp.w = prmt_hi(ub[6], ub[7]);
                    lp.x = cvt_bf16x2(lo[1], lo[0]); lp.y = cvt_bf16x2(lo[3], lo[2]);
                    lp.z = cvt_bf16x2(lo[5], lo[4]); lp.w = cvt_bf16x2(lo[7], lo[6]);
                    uint32_t off = (uint32_t)((t >> 3) * 1024 + (t & 7) * 128 + g8 * 16);
                    uint32_t sw  = off ^ ((off >> 3) & 0x70);
                    *(uint4*)(abp + OFF_A_HI + sw) = hp;
                    *(uint4*)(abp + OFF_A_LO + sw) = lp;
                }
                CP_WAIT0();
                FENCE_ASYNC_SHARED();
                __syncthreads();
                if (wid == 0 && elect_one()) {
                    u64 dAh = make_desc(ab + OFF_A_HI), dAl = make_desc(ab + OFF_A_LO);
                    u64 dBh = make_desc(ab + OFF_B_HI), dBl = make_desc(ab + OFF_B_LO);
                    u64 pA[3] = {dAh, dAh, dAl};
                    u64 pB[3] = {dBh, dBl, dBh};
                    #pragma unroll
                    for (int p = 0; p < 3; p++) {
                        #pragma unroll
                        for (int s = 0; s < 4; s++) {
                            uint32_t en = (kc == 0 && p == 0 && s == 0) ? 0u : 1u;
                            u64 ad = pA[p] + s * 2;
                            mma_f16_ss(tmem,      ad, pB[p] + s * 2,       IDESC_W, en);
                            mma_f16_ss(tmem + 80, ad, pB[p] + 640 + s * 2, IDESC_W, en);
                        }
                    }
                    TCGEN05_COMMIT(mbar);
                }
            }
            MBAR_WAIT(mbar, mph); mph ^= 1;

            // ---- gate -> bf16 A2: 8 warps; W1 copy async on warps 4-9 ----
            copy_w2(ab, w2h, w2l, tid);
            if (tid < 256) {
                TCGEN05_FENCE_AFTER();
                const int t = tid & 127;
                const int half = tid >> 7;
                uint32_t da[32], dg[32];
                if (half == 0) {
                    #pragma unroll
                    for (int ch = 0; ch < 2; ch++) {
                        int a0 = ch * 32;
                        LDTM_X32(da, tmem + a0); LDTM_X32(dg, tmem + 80 + a0);
                        TCGEN05_WAIT_LD();
                        float gv[32];
                        for (int i = 0; i < 32; i++) {
                            float a = __uint_as_float(da[i]) + s_bias[a0 + i];
                            float g = __uint_as_float(dg[i]) + s_bias[80 + a0 + i];
                            gv[i] = gatef(a, g);
                        }
                        #pragma unroll
                        for (int q = 0; q < 4; q++)
                            pack8(abp, t, (a0 >> 3) + q, gv + q * 8);
                    }
                } else {
                    LDTM_X16(da, tmem + 64); LDTM_X16(dg, tmem + 144);
                    TCGEN05_WAIT_LD();
                    float gv[16];
                    for (int i = 0; i < 16; i++) {
                        float a = __uint_as_float(da[i]) + s_bias[64 + i];
                        float g = __uint_as_float(dg[i]) + s_bias[144 + i];
                        gv[i] = gatef(a, g);
                    }
                    pack8(abp, t, 8, gv);
                    pack8(abp, t, 9, gv + 8);
                }
            }
            CP_WAIT0();
            FENCE_ASYNC_SHARED();
            __syncthreads();
            if (wid == 0 && elect_one()) issue_gemm2(tmem + 160, ab, mbar);
            MBAR_WAIT(mbar, mph); mph ^= 1;

            if (!FUSE) {
                if (tid < 256) {
                    TCGEN05_FENCE_AFTER();
                    const int t = tid & 127;
                    const int half = tid >> 7;
                    const bool tv = (t0 + t) < Tout;
                    uint32_t d[32];
                    if (half == 0) {
                        #pragma unroll
                        for (int ch = 0; ch < 2; ch++) {
                            int a0 = ch * 32;
                            LDTM_X32(d, tmem + 160 + a0);
                            TCGEN05_WAIT_LD();
                            if (tv) {
                                for (int i = 0; i < 32; i++) {
                                    int c = a0 + i;
                                    float v = __uint_as_float(d[i]) + s_bias[160 + c];
                                    if (RESID) v += __ldg(xin_n + (size_t)c * TinLd + S * (t0 + t) + 3);
                                    xout[((size_t)n * 80 + c) * ToutLd + t0 + t] = v;
                                }
                            }
                        }
                    } else {
                        LDTM_X16(d, tmem + 160 + 64);
                        TCGEN05_WAIT_LD();
                        if (tv) {
                            for (int i = 0; i < 16; i++) {
                                int c = 64 + i;
                                float v = __uint_as_float(d[i]) + s_bias[160 + c];
                                if (RESID) v += __ldg(xin_n + (size_t)c * TinLd + S * (t0 + t) + 3);
                                xout[((size_t)n * 80 + c) * ToutLd + t0 + t] = v;
                            }
                        }
                    }
                }
            } else {
                copy_w2(ab, wf0s, wf0s + 20480, tid);
                if (tid < 256) {
                    TCGEN05_FENCE_AFTER();
                    const int t = tid & 127;
                    const int half = tid >> 7;
                    const bool tv = (t0 + t) < Tout;
                    uint32_t d[32];
                    if (half == 0) {
                        #pragma unroll
                        for (int ch = 0; ch < 2; ch++) {
                            int a0 = ch * 32;
                            LDTM_X32(d, tmem + 160 + a0);
                            TCGEN05_WAIT_LD();
                            float v[32];
                            for (int i = 0; i < 32; i++) {
                                int c = a0 + i;
                                v[i] = __uint_as_float(d[i]) + s_bias[160 + c];
                                if (tv) v[i] += __ldg(xin_n + (size_t)c * TinLd + S * (t0 + t) + 3);
                            }
                            #pragma unroll
                            for (int q = 0; q < 4; q++)
                                pack8(abp, t, (a0 >> 3) + q, v + q * 8);
                        }
                    } else {
                        LDTM_X16(d, tmem + 160 + 64);
                        TCGEN05_WAIT_LD();
                        float v[16];
                        for (int i = 0; i < 16; i++) {
                            int c = 64 + i;
                            v[i] = __uint_as_float(d[i]) + s_bias[160 + c];
                            if (tv) v[i] += __ldg(xin_n + (size_t)c * TinLd + S * (t0 + t) + 3);
                        }
                        pack8(abp, t, 8, v);
                        pack8(abp, t, 9, v + 8);
                    }
                }
                CP_WAIT0();
                FENCE_ASYNC_SHARED();
                __syncthreads();
                if (wid == 0 && elect_one()) issue_gemm2(tmem + 0, ab, mbar);
                MBAR_WAIT(mbar, mph); mph ^= 1;

                copy_w2(ab, wf1s, wf1s + 20480, tid);
                if (tid < 256) {
                    TCGEN05_FENCE_AFTER();
                    const int t = tid & 127;
                    const int half = tid >> 7;
                    uint32_t d[32];
                    if (half == 0) {
                        #pragma unroll
                        for (int ch = 0; ch < 2; ch++) {
                            int a0 = ch * 32;
                            LDTM_X32(d, tmem + a0);
                            TCGEN05_WAIT_LD();
                            float v[32];
                            for (int i = 0; i < 32; i++)
                                v[i] = fmaxf(__uint_as_float(d[i]) + s_bias[240 + a0 + i], 0.f);
                            #pragma unroll
                            for (int q = 0; q < 4; q++)
                                pack8(abp, t, (a0 >> 3) + q, v + q * 8);
                        }
                    } else {
                        LDTM_X16(d, tmem + 64);
                        TCGEN05_WAIT_LD();
                        float v[16];
                        for (int i = 0; i < 16; i++)
                            v[i] = fmaxf(__uint_as_float(d[i]) + s_bias[240 + 64 + i], 0.f);
                        pack8(abp, t, 8, v);
                        pack8(abp, t, 9, v + 8);
                    }
                }
                CP_WAIT0();
                FENCE_ASYNC_SHARED();
                __syncthreads();
                if (wid == 0 && elect_one()) issue_gemm2(tmem + 80, ab, mbar);
                MBAR_WAIT(mbar, mph); mph ^= 1;

                if (tid < 256) {
                    TCGEN05_FENCE_AFTER();
                    const int t = tid & 127;
                    const int half = tid >> 7;
                    const bool tv = (t0 + t) < Tout;
                    uint32_t d[32];
                    if (half == 0) {
                        #pragma unroll
                        for (int ch = 0; ch < 2; ch++) {
                            int a0 = ch * 32;
                            LDTM_X32(d, tmem + 80 + a0);
                            TCGEN05_WAIT_LD();
                            if (tv) {
                                float* dst = xout + ((size_t)n * Tout + t0 + t) * 80 + a0;
                                for (int i = 0; i < 32; i += 4) {
                                    float4 o;
                                    o.x = __uint_as_float(d[i])     + s_bias[320 + a0 + i];
                                    o.y = __uint_as_float(d[i + 1]) + s_bias[320 + a0 + i + 1];
                                    o.z = __uint_as_float(d[i + 2]) + s_bias[320 + a0 + i + 2];
                                    o.w = __uint_as_float(d[i + 3]) + s_bias[320 + a0 + i + 3];
                                    *(float4*)(dst + i) = o;
                                }
                            }
                        }
                    } else {
                        LDTM_X16(d, tmem + 80 + 64);
                        TCGEN05_WAIT_LD();
                        if (tv) {
                            float* dst = xout + ((size_t)n * Tout + t0 + t) * 80 + 64;
                            for (int i = 0; i < 16; i += 4) {
                                float4 o;
                                o.x = __uint_as_float(d[i])     + s_bias[320 + 64 + i];
                                o.y = __uint_as_float(d[i + 1]) + s_bias[320 + 64 + i + 1];
                                o.z = __uint_as_float(d[i + 2]) + s_bias[320 + 64 + i + 2];
                                o.w = __uint_as_float(d[i + 3]) + s_bias[320 + 64 + i + 3];
                                *(float4*)(dst + i) = o;
                            }
                        }
                    }
                }
            }
#else
            // ------- safe scalar fallback (never runs on GB300) -------
            float* gsmF = (float*)(abp);
            float* bufF = (float*)(abp + 43008);
            __syncthreads();
            for (int e = tid; e < 80 * 128; e += 320) {
                int oc = e >> 7, tt = e & 127;
                float a = s_bias[oc], g = s_bias[oc + 80];
                for (int c = 0; c < 80; c++) {
                    for (int j = 0; j < 4; j++) {
                        int u = S * (t0 + tt) + j;
                        float xv = (u < Tin)
                                 ? (FIRST ? xin_n[(size_t)u * 80 + c]
                                          : xin_n[(size_t)c * TinLd + u]) : 0.f;
                        float wa = __bfloat162float(wbh[oc * 320 + c * 4 + j])
                                 + __bfloat162float(wbl[oc * 320 + c * 4 + j]);
                        float wg = __bfloat162float(wbh[(oc + 80) * 320 + c * 4 + j])
                                 + __bfloat162float(wbl[(oc + 80) * 320 + c * 4 + j]);
                        a = fmaf(wa, xv, a);
                        g = fmaf(wg, xv, g);
                    }
                }
                gsmF[oc * 132 + tt] = gatef(a, g);
            }
            __syncthreads();
            for (int e = tid; e < 80 * 128; e += 320) {
                int oc = e >> 7, tt = e & 127;
                int t = t0 + tt;
                float s = s_bias[160 + oc];
                for (int ic = 0; ic < 80; ic++)
                    s = fmaf(g_w1t[l * 6400 + ic * 80 + oc], gsmF[ic * 132 + tt], s);
                if (RESID && t < Tout) s += xin_n[(size_t)oc * TinLd + S * t + 3];
                if (FUSE) bufF[oc * 132 + tt] = s;
                else if (t < Tout) xout[((size_t)n * 80 + oc) * ToutLd + t] = s;
            }
            if (FUSE) {
                __syncthreads();
                for (int e = tid; e < 80 * 128; e += 320) {
                    int oc = e >> 7, tt = e & 127;
                    float s = s_bias[240 + oc];
                    for (int ic = 0; ic < 80; ic++)
                        s = fmaf(g_wf0t[ic * 80 + oc], bufF[ic * 132 + tt], s);
                    gsmF[oc * 132 + tt] = fmaxf(s, 0.f);
                }
                __syncthreads();
                for (int e = tid; e < 80 * 128; e += 320) {
                    int oc = e >> 7, tt = e & 127;
                    int t = t0 + tt;
                    if (t < Tout) {
                        float s = s_bias[320 + oc];
                        for (int ic = 0; ic < 80; ic++)
                            s = fmaf(g_wf1t[ic * 80 + oc], gsmF[ic * 132 + tt], s);
                        xout[((size_t)n * Tout + t) * 80 + oc] = s;
                    }
                }
            }
#endif
            __threadfence();
            __syncthreads();
            if (tid == 0) atomicAdd(&g_done[l][n], 1u);

        } else {
            // ================= VQ tile =================
            const int loc = (int)(tk - 1600);
            const int n = loc / 16, bxv = loc % 16;
            const int t0 = bxv * 128;

            if (tid == 0) {
                while (atomicAdd(&g_done[3][n], 0u) < 20u) __nanosleep(200);
                __threadfence();
                sm0 = 0u; sm1 = 0u;
            }
            __syncthreads();

#if HAS_TC
            {
                const float4* src = (const float4*)(eS + (size_t)n * 2040 * 80);
                for (int gi = tid; gi < 1280; gi += 320) {
                    int t = gi / 10, kg = gi % 10;
                    int tg = t0 + t;
                    float v[8] = {0.f, 0.f, 0.f, 0.f, 0.f, 0.f, 0.f, 0.f};
                    if (tg < 2040) {
                        float4 a = __ldg(src + (size_t)tg * 20 + kg * 2);
                        float4 b = __ldg(src + (size_t)tg * 20 + kg * 2 + 1);
                        v[0] = a.x; v[1] = a.y; v[2] = a.z; v[3] = a.w;
                        v[4] = b.x; v[5] = b.y; v[6] = b.z; v[7] = b.w;
                    }
                    pack8(abp, t, kg, v);
                }
            }
            const int sub  = wid & 3;
            const int quar = wid >> 2;
            const int t    = sub * 32 + (tid & 31);
            float best = 3.4e38f;
            int   bi   = 0;

            for (int grp = 0; grp < 2; grp++) {
                for (int ch = 0; ch < 4; ch++) {
                    int cls = grp * 4 + ch;
                    for (int i = tid; i < 1024; i += 320) {
                        CP_ASYNC16(ab + VQ_B_HI + i * 16, (const char*)(g_embs[0][cls]) + (size_t)i * 16);
                        CP_ASYNC16(ab + VQ_B_LO + i * 16, (const char*)(g_embs[1][cls]) + (size_t)i * 16);
                    }
                    CP_COMMIT();
                    CP_WAIT0();
                    FENCE_ASYNC_SHARED();
                    __syncthreads();
                    if (wid == 0 && elect_one()) issue_gemmv(tmem + ch * 64, ab, mbar);
                    MBAR_WAIT(mbar, mph); mph ^= 1;
                }
                TCGEN05_FENCE_AFTER();
                if (wid < 8) {
                    uint32_t d[32];
                    #pragma unroll
                    for (int cc = 0; cc < 4; cc++) {
                        int c0 = quar * 128 + cc * 32;
                        LDTM_X32(d, tmem + c0);
                        TCGEN05_WAIT_LD();
                        for (int i = 0; i < 32; i++) {
                            int k = grp * 256 + c0 + i;
                            float dd = se2[k] - 2.f * __uint_as_float(d[i]);
                            if (dd < best) { best = dd; bi = k; }
                        }
                    }
                    TCGEN05_FENCE_BEFORE();
                }
                __syncthreads();
            }
            if (wid < 8) {
                sdist[t * 2 + quar] = best;
                sidx [t * 2 + quar] = bi;
            }
            __syncthreads();

            if (tid < 128) {
                float d0 = sdist[tid * 2],     d1 = sdist[tid * 2 + 1];
                int   i0 = sidx [tid * 2],     i1 = sidx [tid * 2 + 1];
                int bbi = (d1 < d0 || (d1 == d0 && i1 < i0)) ? i1 : i0;
                int tg2 = t0 + tid;
                if (tg2 < 2040) {
                    const float* dv = emb + (size_t)bbi * 80;
                    const float* qr = (tg2 < 2016)
                                    ? (eQ + ((size_t)n * 504 + (tg2 % 504)) * 80)
                                    : nullptr;
                    float s0 = blin[0], s1 = blin[1];
                    #pragma unroll 4
                    for (int c = 0; c < 80; c++) {
                        float v = dv[c] + (qr ? qr[c] : 0.f);
                        s0 = fmaf(v, wlin[c],      s0);
                        s1 = fmaf(v, wlin[80 + c], s1);
                    }
                    atomicMax(&sm0, fenc(tanhf(s0)));
                    atomicMax(&sm1, fenc(tanhf(s1)));
                }
            }
            __syncthreads();
#else
            __syncthreads();
            if (tid < 128) {
                int tg2 = t0 + tid;
                if (tg2 < 2040) {
                    const float* xr = eS + ((size_t)n * 2040 + tg2) * 80;
                    float best = 3.4e38f; int bbi = 0;
                    for (int k = 0; k < 512; k++) {
                        float dot = 0.f;
                        for (int c = 0; c < 80; c++) dot = fmaf(xr[c], emb[k * 80 + c], dot);
                        float dd = se2[k] - 2.f * dot;
                        if (dd < best) { best = dd; bbi = k; }
                    }
                    const float* dv = emb + (size_t)bbi * 80;
                    const float* qr = (tg2 < 2016)
                                    ? (eQ + ((size_t)n * 504 + (tg2 % 504)) * 80)
                                    : nullptr;
                    float s0 = blin[0], s1 = blin[1];
                    for (int c = 0; c < 80; c++) {
                        float v = dv[c] + (qr ? qr[c] : 0.f);
                        s0 = fmaf(v, wlin[c],      s0);
                        s1 = fmaf(v, wlin[80 + c], s1);
                    }
                    atomicMax(&sm0, fenc(tanhf(s0)));
                    atomicMax(&sm1, fenc(tanhf(s1)));
                }
            }
            __syncthreads();
#endif
            if (tid == 0) {
                atomicMax(&g_gmax[n * 2 + 0], sm0);
                atomicMax(&g_gmax[n * 2 + 1], sm1);
                __threadfence();
                unsigned old = atomicAdd(&g_cnt[n], 1u);
                if (old == 15u) {
                    unsigned e0 = atomicMax(&g_gmax[n * 2 + 0], 0u);
                    unsigned e1 = atomicMax(&g_gmax[n * 2 + 1], 0u);
                    out[n * 2 + 0] = fdec(e0);
                    out[n * 2 + 1] = fdec(e1);
                }
            }
        }
    }

#if HAS_TC
    __syncthreads();
    if (wid == 0) TCGEN05_DEALLOC(tmem, 256);
#endif
}

// ---------------------------------------------------------------------------
// Host launch
// ---------------------------------------------------------------------------
extern "C" void kernel_launch(void* const* d_in, const int* in_sizes, int n_in,
                              void* d_out, int out_size) {
    const float* search = (const float*)d_in[0];
    const float* query  = (const float*)d_in[1];
    const float* w_wide = (const float*)d_in[2];
    const float* b_wide = (const float*)d_in[3];
    const float* w_1x1  = (const float*)d_in[4];
    const float* b_1x1  = (const float*)d_in[5];
    const float* w_f0   = (const float*)d_in[6];
    const float* b_f0   = (const float*)d_in[7];
    const float* w_f1   = (const float*)d_in[8];
    const float* b_f1   = (const float*)d_in[9];
    const float* emb    = (const float*)d_in[10];
    const float* w_lin  = (const float*)d_in[11];
    const float* b_lin  = (const float*)d_in[12];
    float* out = (float*)d_out;

    void *pA, *pB, *pAq, *pBq, *pS, *pQ, *pwh, *pwl, *pw1s, *pwf0s, *pwf1s;
    cudaGetSymbolAddress(&pA,   g_bufA);
    cudaGetSymbolAddress(&pB,   g_bufB);
    cudaGetSymbolAddress(&pAq,  g_bufAq);
    cudaGetSymbolAddress(&pBq,  g_bufBq);
    cudaGetSymbolAddress(&pS,   g_encS);
    cudaGetSymbolAddress(&pQ,   g_encQ);
    cudaGetSymbolAddress(&pwh,  g_wbh);
    cudaGetSymbolAddress(&pwl,  g_wbl);
    cudaGetSymbolAddress(&pw1s, g_w1s);
    cudaGetSymbolAddress(&pwf0s, g_wf0s);
    cudaGetSymbolAddress(&pwf1s, g_wf1s);
    float* A   = (float*)pA;
    float* B   = (float*)pB;
    float* Aq  = (float*)pAq;
    float* Bq  = (float*)pBq;
    float* eS  = (float*)pS;
    float* eQ  = (float*)pQ;
    __nv_bfloat16* wbh = (__nv_bfloat16*)pwh;
    __nv_bfloat16* wbl = (__nv_bfloat16*)pwl;
    const char* w1s  = (const char*)pw1s;
    const char* wf0s = (const char*)pwf0s;
    const char* wf1s = (const char*)pwf1s;

    cudaFuncSetAttribute(mega_kernel,
                         cudaFuncAttributeMaxDynamicSharedMemorySize, SMEM_DYN);

    prep_kernel<<<80, 256>>>(w_wide, w_1x1, w_f0, w_f1, emb);

    mega_kernel<<<296, 320, SMEM_DYN>>>(
        search, query, A, Aq, B, Bq, eS, eQ,
        wbh, wbl, b_wide, b_1x1,
        w1s, wf0s, wf1s, b_f0, b_f1,
        emb, w_lin, b_lin, out);
}